// round 1
// baseline (speedup 1.0000x reference)
#include <cuda_runtime.h>
#include <cstdio>

#define BATCH 4
#define CHN   256
#define HH    256
#define WW    256
#define NROI  2048
#define FDIM  2304   // 9 * 256
#define DDIM  256

// ---------------- scratch (device globals; no allocation) ----------------
__device__ float g_fmT[(size_t)BATCH * HH * WW * CHN];   // NHWC transposed feature map
__device__ float g_x  [(size_t)NROI * FDIM];             // pooled features, bin-major
__device__ float g_h1 [NROI * DDIM];
__device__ float g_sh [NROI * DDIM];
__device__ float g_t1 [NROI * DDIM];
__device__ float g_hc [NROI * DDIM];
__device__ float g_t2 [NROI * DDIM];
__device__ float g_hi [NROI * DDIM];
__device__ float g_t3 [NROI * DDIM];
__device__ float g_hr [NROI * DDIM];

// ---------------- NCHW -> NHWC transpose ----------------
__global__ __launch_bounds__(256) void transpose_k(const float* __restrict__ fm) {
    __shared__ float tile[32][33];
    const int bw = blockIdx.x * 32;          // w tile
    const int bc = blockIdx.y * 32;          // c tile
    const int bh = blockIdx.z;               // b*H + h
    const int b  = bh >> 8;
    const int h  = bh & 255;
    const int tx = threadIdx.x;
    // read fm[b][bc+i][h][bw+tx] (coalesced along w)
    #pragma unroll
    for (int i = threadIdx.y; i < 32; i += 8) {
        tile[i][tx] = fm[((((size_t)b * CHN + (bc + i)) * HH + h) * WW) + bw + tx];
    }
    __syncthreads();
    // write fmT[b][h][bw+i][bc+tx] (coalesced along c)
    #pragma unroll
    for (int i = threadIdx.y; i < 32; i += 8) {
        g_fmT[((((size_t)b * HH + h) * WW + (bw + i)) * CHN) + bc + tx] = tile[tx][i];
    }
}

// ---------------- RoIAlignRotated (one block per roi, thread = channel) ----------------
__global__ __launch_bounds__(256) void roi_k(const float* __restrict__ boxes,
                                             const int* __restrict__ bidx) {
    const int n = blockIdx.x;
    const int c = threadIdx.x;

    const float gwf = 102.4f / 256.0f;
    const float bx  = boxes[n * 7 + 0];
    const float by  = boxes[n * 7 + 1];
    const float rh_m = boxes[n * 7 + 4];
    const float rw_m = boxes[n * 7 + 5];
    const float ang  = boxes[n * 7 + 6];

    const float cx = (bx - (-51.2f)) / gwf - 0.5f;
    const float cy = (by - (-51.2f)) / gwf - 0.5f;
    const float w  = rw_m / gwf;
    const float h  = rh_m / gwf;
    const float theta = -ang;
    const float ct = cosf(theta);
    const float st = sinf(theta);
    const float bin_h = h * (1.0f / 3.0f);
    const float bin_w = w * (1.0f / 3.0f);

    const int b = bidx[n];
    const float* __restrict__ fb = g_fmT + (size_t)b * HH * WW * CHN;

    #pragma unroll
    for (int oh = 0; oh < 3; oh++) {
        #pragma unroll
        for (int ow = 0; ow < 3; ow++) {
            float acc = 0.0f;
            #pragma unroll
            for (int iy = 0; iy < 2; iy++) {
                #pragma unroll
                for (int ix = 0; ix < 2; ix++) {
                    const float yy = -h * 0.5f + ((float)oh + ((float)iy + 0.5f) * 0.5f) * bin_h;
                    const float xx = -w * 0.5f + ((float)ow + ((float)ix + 0.5f) * 0.5f) * bin_w;
                    float y = yy * ct - xx * st + cy;
                    float x = yy * st + xx * ct + cx;
                    const bool valid = (y > -1.0f) && (y < (float)HH) && (x > -1.0f) && (x < (float)WW);
                    if (valid) {
                        y = fminf(fmaxf(y, 0.0f), (float)(HH - 1));
                        x = fminf(fmaxf(x, 0.0f), (float)(WW - 1));
                        int y0 = min((int)y, HH - 1);
                        int x0 = min((int)x, WW - 1);
                        int y1 = min(y0 + 1, HH - 1);
                        int x1 = min(x0 + 1, WW - 1);
                        const float ly = y - (float)y0;
                        const float lx = x - (float)x0;
                        const float hy = 1.0f - ly;
                        const float hx = 1.0f - lx;
                        const float v00 = fb[(((size_t)y0 * WW) + x0) * CHN + c];
                        const float v01 = fb[(((size_t)y0 * WW) + x1) * CHN + c];
                        const float v10 = fb[(((size_t)y1 * WW) + x0) * CHN + c];
                        const float v11 = fb[(((size_t)y1 * WW) + x1) * CHN + c];
                        acc += hy * hx * v00 + hy * lx * v01 + ly * hx * v10 + ly * lx * v11;
                    }
                }
            }
            g_x[(size_t)n * FDIM + (oh * 3 + ow) * CHN + c] = acc * 0.25f;
        }
    }
}

// ---------------- fp32 GEMM: C[M,N] = act(A[M,K] @ B[N,K]^T) ----------------
// 64x64 block tile, 4x4 microtile, 256 threads, BK=16, stride-65 smem padding.
__global__ __launch_bounds__(256) void gemm_bt(const float* __restrict__ A,
                                               const float* __restrict__ B,
                                               float* __restrict__ C,
                                               int M, int N, int K, int doRelu) {
    __shared__ float As[16][65];
    __shared__ float Bs[16][65];

    const int tid = threadIdx.x;
    const int tx = tid & 15;      // column group
    const int ty = tid >> 4;      // row group
    const int bm = blockIdx.y * 64;
    const int bn = blockIdx.x * 64;

    float acc[4][4] = {};

    const int lm = tid >> 2;           // 0..63: row within tile
    const int lk = (tid & 3) * 4;      // 0,4,8,12
    const float* Ag = A + (size_t)(bm + lm) * K + lk;
    const float* Bg = B + (size_t)(bn + lm) * K + lk;

    for (int k0 = 0; k0 < K; k0 += 16) {
        const float4 av = *(const float4*)(Ag + k0);
        const float4 bv = *(const float4*)(Bg + k0);
        As[lk + 0][lm] = av.x; As[lk + 1][lm] = av.y;
        As[lk + 2][lm] = av.z; As[lk + 3][lm] = av.w;
        Bs[lk + 0][lm] = bv.x; Bs[lk + 1][lm] = bv.y;
        Bs[lk + 2][lm] = bv.z; Bs[lk + 3][lm] = bv.w;
        __syncthreads();

        #pragma unroll
        for (int k = 0; k < 16; k++) {
            float a[4], bb[4];
            #pragma unroll
            for (int i = 0; i < 4; i++) a[i] = As[k][ty * 4 + i];
            #pragma unroll
            for (int j = 0; j < 4; j++) bb[j] = Bs[k][tx * 4 + j];
            #pragma unroll
            for (int i = 0; i < 4; i++)
                #pragma unroll
                for (int j = 0; j < 4; j++)
                    acc[i][j] += a[i] * bb[j];
        }
        __syncthreads();
    }

    #pragma unroll
    for (int i = 0; i < 4; i++) {
        #pragma unroll
        for (int j = 0; j < 4; j++) {
            float v = acc[i][j];
            if (doRelu) v = fmaxf(v, 0.0f);
            C[(size_t)(bm + ty * 4 + i) * N + bn + tx * 4 + j] = v;
        }
    }
}

// ---------------- final heads: 9 dot products per roi ----------------
__global__ __launch_bounds__(288) void heads_k(const float* __restrict__ hc,
                                               const float* __restrict__ hi,
                                               const float* __restrict__ hr,
                                               const float* __restrict__ w_cls3,
                                               const float* __restrict__ b_cls3,
                                               const float* __restrict__ w_iou3,
                                               const float* __restrict__ b_iou3,
                                               const float* __restrict__ w_reg3,
                                               const float* __restrict__ b_reg3,
                                               float* __restrict__ out) {
    const int n = blockIdx.x;
    const int warp = threadIdx.x >> 5;   // 0..8
    const int lane = threadIdx.x & 31;

    const float* h;
    const float* w;
    float bias;
    float* o;
    if (warp == 0)      { h = hc + (size_t)n * DDIM; w = w_cls3;              bias = b_cls3[0];      o = out + n; }
    else if (warp == 1) { h = hi + (size_t)n * DDIM; w = w_iou3;              bias = b_iou3[0];      o = out + NROI + n; }
    else { const int j = warp - 2;
           h = hr + (size_t)n * DDIM; w = w_reg3 + j * DDIM; bias = b_reg3[j]; o = out + 2 * NROI + n * 7 + j; }

    float s = 0.0f;
    #pragma unroll
    for (int i = lane; i < DDIM; i += 32) s += h[i] * w[i];
    #pragma unroll
    for (int off = 16; off; off >>= 1) s += __shfl_xor_sync(0xffffffffu, s, off);
    if (lane == 0) *o = s + bias;
}

// ---------------- launch ----------------
extern "C" void kernel_launch(void* const* d_in, const int* in_sizes, int n_in,
                              void* d_out, int out_size) {
    const float* fm     = (const float*)d_in[0];
    const float* boxes  = (const float*)d_in[1];
    const int*   bidx   = (const int*)  d_in[2];
    const float* w_sh1  = (const float*)d_in[3];
    const float* w_sh2  = (const float*)d_in[4];
    const float* w_cls1 = (const float*)d_in[5];
    const float* w_cls2 = (const float*)d_in[6];
    const float* w_cls3 = (const float*)d_in[7];
    const float* b_cls3 = (const float*)d_in[8];
    const float* w_iou1 = (const float*)d_in[9];
    const float* w_iou2 = (const float*)d_in[10];
    const float* w_iou3 = (const float*)d_in[11];
    const float* b_iou3 = (const float*)d_in[12];
    const float* w_reg1 = (const float*)d_in[13];
    const float* w_reg2 = (const float*)d_in[14];
    const float* w_reg3 = (const float*)d_in[15];
    const float* b_reg3 = (const float*)d_in[16];

    float *px, *ph1, *psh, *pt1, *phc, *pt2, *phi, *pt3, *phr;
    cudaGetSymbolAddress((void**)&px,  g_x);
    cudaGetSymbolAddress((void**)&ph1, g_h1);
    cudaGetSymbolAddress((void**)&psh, g_sh);
    cudaGetSymbolAddress((void**)&pt1, g_t1);
    cudaGetSymbolAddress((void**)&phc, g_hc);
    cudaGetSymbolAddress((void**)&pt2, g_t2);
    cudaGetSymbolAddress((void**)&phi, g_hi);
    cudaGetSymbolAddress((void**)&pt3, g_t3);
    cudaGetSymbolAddress((void**)&phr, g_hr);

    // 1) NCHW -> NHWC
    transpose_k<<<dim3(WW / 32, CHN / 32, BATCH * HH), dim3(32, 8)>>>(fm);

    // 2) rotated roi-align -> g_x [N, 2304]
    roi_k<<<NROI, CHN>>>(boxes, bidx);

    // 3) shared MLP
    gemm_bt<<<dim3(DDIM / 64, NROI / 64), 256>>>(px,  w_sh1, ph1, NROI, DDIM, FDIM, 1);
    gemm_bt<<<dim3(DDIM / 64, NROI / 64), 256>>>(ph1, w_sh2, psh, NROI, DDIM, DDIM, 1);

    // 4) three heads (2-layer MLPs)
    gemm_bt<<<dim3(DDIM / 64, NROI / 64), 256>>>(psh, w_cls1, pt1, NROI, DDIM, DDIM, 1);
    gemm_bt<<<dim3(DDIM / 64, NROI / 64), 256>>>(pt1, w_cls2, phc, NROI, DDIM, DDIM, 1);
    gemm_bt<<<dim3(DDIM / 64, NROI / 64), 256>>>(psh, w_iou1, pt2, NROI, DDIM, DDIM, 1);
    gemm_bt<<<dim3(DDIM / 64, NROI / 64), 256>>>(pt2, w_iou2, phi, NROI, DDIM, DDIM, 1);
    gemm_bt<<<dim3(DDIM / 64, NROI / 64), 256>>>(psh, w_reg1, pt3, NROI, DDIM, DDIM, 1);
    gemm_bt<<<dim3(DDIM / 64, NROI / 64), 256>>>(pt3, w_reg2, phr, NROI, DDIM, DDIM, 1);

    // 5) final projections -> d_out (cls[2048] | iou[2048] | reg[2048*7])
    heads_k<<<NROI, 288>>>(phc, phi, phr, w_cls3, b_cls3, w_iou3, b_iou3,
                           w_reg3, b_reg3, (float*)d_out);
}

// round 5
// speedup vs baseline: 1.8734x; 1.8734x over previous
#include <cuda_runtime.h>

#define BATCH 4
#define CHN   256
#define HH    256
#define WW    256
#define NROI  2048
#define FDIM  2304   // 9 * 256
#define DDIM  256

// ---------------- scratch (device globals; no allocation) ----------------
__device__ float g_fmT[(size_t)BATCH * HH * WW * CHN];   // NHWC feature map
__device__ float g_x  [(size_t)NROI * FDIM];             // pooled features
__device__ float g_h1 [NROI * DDIM];
__device__ float g_sh [NROI * DDIM];
__device__ float g_t0 [NROI * DDIM];
__device__ float g_t1 [NROI * DDIM];
__device__ float g_t2 [NROI * DDIM];
__device__ float g_o0 [NROI * DDIM];
__device__ float g_o1 [NROI * DDIM];
__device__ float g_o2 [NROI * DDIM];

// ---------------- NCHW -> NHWC transpose ----------------
__global__ __launch_bounds__(256) void transpose_k(const float* __restrict__ fm) {
    __shared__ float tile[32][33];
    const int bw = blockIdx.x * 32;
    const int bc = blockIdx.y * 32;
    const int bh = blockIdx.z;               // b*H + h
    const int b  = bh >> 8;
    const int h  = bh & 255;
    const int tx = threadIdx.x;
    #pragma unroll
    for (int i = threadIdx.y; i < 32; i += 8) {
        tile[i][tx] = fm[((((size_t)b * CHN + (bc + i)) * HH + h) * WW) + bw + tx];
    }
    __syncthreads();
    #pragma unroll
    for (int i = threadIdx.y; i < 32; i += 8) {
        g_fmT[((((size_t)b * HH + h) * WW + (bw + i)) * CHN) + bc + tx] = tile[tx][i];
    }
}

// ---------------- RoIAlignRotated (block = roi, thread = channel) ----------------
__global__ __launch_bounds__(256) void roi_k(const float* __restrict__ boxes,
                                             const int* __restrict__ bidx) {
    const int n = blockIdx.x;
    const int c = threadIdx.x;

    const float gwf  = 102.4f / 256.0f;
    const float bx   = boxes[n * 7 + 0];
    const float by   = boxes[n * 7 + 1];
    const float rh_m = boxes[n * 7 + 4];
    const float rw_m = boxes[n * 7 + 5];
    const float ang  = boxes[n * 7 + 6];

    const float cx = (bx + 51.2f) / gwf - 0.5f;
    const float cy = (by + 51.2f) / gwf - 0.5f;
    const float w  = rw_m / gwf;
    const float h  = rh_m / gwf;
    const float ct = cosf(-ang);
    const float st = sinf(-ang);
    const float bin_h = h * (1.0f / 3.0f);
    const float bin_w = w * (1.0f / 3.0f);

    const int b = bidx[n];
    const float* __restrict__ fb = g_fmT + (size_t)b * HH * WW * CHN;

    #pragma unroll
    for (int oh = 0; oh < 3; oh++) {
        #pragma unroll
        for (int ow = 0; ow < 3; ow++) {
            float acc = 0.0f;
            #pragma unroll
            for (int iy = 0; iy < 2; iy++) {
                #pragma unroll
                for (int ix = 0; ix < 2; ix++) {
                    const float yy = -h * 0.5f + ((float)oh + ((float)iy + 0.5f) * 0.5f) * bin_h;
                    const float xx = -w * 0.5f + ((float)ow + ((float)ix + 0.5f) * 0.5f) * bin_w;
                    float y = yy * ct - xx * st + cy;
                    float x = yy * st + xx * ct + cx;
                    const bool valid = (y > -1.0f) && (y < (float)HH) && (x > -1.0f) && (x < (float)WW);
                    if (valid) {
                        y = fminf(fmaxf(y, 0.0f), (float)(HH - 1));
                        x = fminf(fmaxf(x, 0.0f), (float)(WW - 1));
                        int y0 = min((int)y, HH - 1);
                        int x0 = min((int)x, WW - 1);
                        int y1 = min(y0 + 1, HH - 1);
                        int x1 = min(x0 + 1, WW - 1);
                        const float ly = y - (float)y0;
                        const float lx = x - (float)x0;
                        const float hy = 1.0f - ly;
                        const float hx = 1.0f - lx;
                        const float v00 = fb[(((size_t)y0 * WW) + x0) * CHN + c];
                        const float v01 = fb[(((size_t)y0 * WW) + x1) * CHN + c];
                        const float v10 = fb[(((size_t)y1 * WW) + x0) * CHN + c];
                        const float v11 = fb[(((size_t)y1 * WW) + x1) * CHN + c];
                        acc += hy * hx * v00 + hy * lx * v01 + ly * hx * v10 + ly * lx * v11;
                    }
                }
            }
            g_x[(size_t)n * FDIM + (oh * 3 + ow) * CHN + c] = acc * 0.25f;
        }
    }
}

// ---------------- fp32 GEMM: C[M,N] = relu(A[M,K] @ B[N,K]^T), batched x3 via blockIdx.z
// 64x64 tile, 4x4 microtile, 256 threads, BK=16, double-buffered smem, float4 paths.
__global__ __launch_bounds__(256) void gemm3_k(
    const float* __restrict__ A0, const float* __restrict__ A1, const float* __restrict__ A2,
    const float* __restrict__ B0, const float* __restrict__ B1, const float* __restrict__ B2,
    float* __restrict__ C0, float* __restrict__ C1, float* __restrict__ C2,
    int M, int N, int K)
{
    const int z = blockIdx.z;
    const float* __restrict__ A = (z == 0) ? A0 : (z == 1) ? A1 : A2;
    const float* __restrict__ B = (z == 0) ? B0 : (z == 1) ? B1 : B2;
    float* __restrict__ C       = (z == 0) ? C0 : (z == 1) ? C1 : C2;

    __shared__ __align__(16) float As[2][16][68];
    __shared__ __align__(16) float Bs[2][16][68];

    const int tid = threadIdx.x;
    const int row = tid >> 2;            // 0..63
    const int lk  = (tid & 3) * 4;       // 0,4,8,12
    const int bm  = blockIdx.y * 64;
    const int bn  = blockIdx.x * 64;
    const int ty  = tid >> 4;            // 0..15
    const int tx  = tid & 15;            // 0..15

    const float* Ag = A + (size_t)(bm + row) * K + lk;
    const float* Bg = B + (size_t)(bn + row) * K + lk;

    float acc[4][4] = {};

    // prologue: fill buffer 0
    {
        const float4 av = *(const float4*)Ag;
        const float4 bv = *(const float4*)Bg;
        As[0][lk + 0][row] = av.x; As[0][lk + 1][row] = av.y;
        As[0][lk + 2][row] = av.z; As[0][lk + 3][row] = av.w;
        Bs[0][lk + 0][row] = bv.x; Bs[0][lk + 1][row] = bv.y;
        Bs[0][lk + 2][row] = bv.z; Bs[0][lk + 3][row] = bv.w;
    }
    __syncthreads();

    const int nk = K >> 4;
    for (int kb = 0; kb < nk; kb++) {
        const int cur = kb & 1;
        float4 av2, bv2;
        const bool more = (kb + 1 < nk);
        if (more) {
            av2 = *(const float4*)(Ag + (kb + 1) * 16);
            bv2 = *(const float4*)(Bg + (kb + 1) * 16);
        }

        #pragma unroll
        for (int k = 0; k < 16; k++) {
            const float4 a = *(const float4*)&As[cur][k][ty * 4];
            const float4 b = *(const float4*)&Bs[cur][k][tx * 4];
            const float aa[4] = {a.x, a.y, a.z, a.w};
            const float bb[4] = {b.x, b.y, b.z, b.w};
            #pragma unroll
            for (int i = 0; i < 4; i++)
                #pragma unroll
                for (int j = 0; j < 4; j++)
                    acc[i][j] += aa[i] * bb[j];
        }

        if (more) {
            const int nxt = cur ^ 1;
            As[nxt][lk + 0][row] = av2.x; As[nxt][lk + 1][row] = av2.y;
            As[nxt][lk + 2][row] = av2.z; As[nxt][lk + 3][row] = av2.w;
            Bs[nxt][lk + 0][row] = bv2.x; Bs[nxt][lk + 1][row] = bv2.y;
            Bs[nxt][lk + 2][row] = bv2.z; Bs[nxt][lk + 3][row] = bv2.w;
            __syncthreads();
        }
    }

    #pragma unroll
    for (int i = 0; i < 4; i++) {
        float4 v;
        v.x = fmaxf(acc[i][0], 0.0f);
        v.y = fmaxf(acc[i][1], 0.0f);
        v.z = fmaxf(acc[i][2], 0.0f);
        v.w = fmaxf(acc[i][3], 0.0f);
        *(float4*)&C[(size_t)(bm + ty * 4 + i) * N + bn + tx * 4] = v;
    }
}

// ---------------- final heads: 9 dot products per roi ----------------
__global__ __launch_bounds__(288) void heads_k(const float* __restrict__ hc,
                                               const float* __restrict__ hi,
                                               const float* __restrict__ hr,
                                               const float* __restrict__ w_cls3,
                                               const float* __restrict__ b_cls3,
                                               const float* __restrict__ w_iou3,
                                               const float* __restrict__ b_iou3,
                                               const float* __restrict__ w_reg3,
                                               const float* __restrict__ b_reg3,
                                               float* __restrict__ out) {
    const int n = blockIdx.x;
    const int warp = threadIdx.x >> 5;   // 0..8
    const int lane = threadIdx.x & 31;

    const float* h;
    const float* w;
    float bias;
    float* o;
    if (warp == 0)      { h = hc + (size_t)n * DDIM; w = w_cls3;              bias = b_cls3[0]; o = out + n; }
    else if (warp == 1) { h = hi + (size_t)n * DDIM; w = w_iou3;              bias = b_iou3[0]; o = out + NROI + n; }
    else { const int j = warp - 2;
           h = hr + (size_t)n * DDIM; w = w_reg3 + j * DDIM; bias = b_reg3[j]; o = out + 2 * NROI + n * 7 + j; }

    float s = 0.0f;
    #pragma unroll
    for (int i = lane * 4; i < DDIM; i += 128) {
        const float4 hv = *(const float4*)&h[i];
        const float4 wv = *(const float4*)&w[i];
        s += hv.x * wv.x + hv.y * wv.y + hv.z * wv.z + hv.w * wv.w;
    }
    #pragma unroll
    for (int off = 16; off; off >>= 1) s += __shfl_xor_sync(0xffffffffu, s, off);
    if (lane == 0) *o = s + bias;
}

// ---------------- launch ----------------
extern "C" void kernel_launch(void* const* d_in, const int* in_sizes, int n_in,
                              void* d_out, int out_size) {
    const float* fm     = (const float*)d_in[0];
    const float* boxes  = (const float*)d_in[1];
    const int*   bidx   = (const int*)  d_in[2];
    const float* w_sh1  = (const float*)d_in[3];
    const float* w_sh2  = (const float*)d_in[4];
    const float* w_cls1 = (const float*)d_in[5];
    const float* w_cls2 = (const float*)d_in[6];
    const float* w_cls3 = (const float*)d_in[7];
    const float* b_cls3 = (const float*)d_in[8];
    const float* w_iou1 = (const float*)d_in[9];
    const float* w_iou2 = (const float*)d_in[10];
    const float* w_iou3 = (const float*)d_in[11];
    const float* b_iou3 = (const float*)d_in[12];
    const float* w_reg1 = (const float*)d_in[13];
    const float* w_reg2 = (const float*)d_in[14];
    const float* w_reg3 = (const float*)d_in[15];
    const float* b_reg3 = (const float*)d_in[16];

    float *px, *ph1, *psh, *pt0, *pt1, *pt2, *po0, *po1, *po2;
    cudaGetSymbolAddress((void**)&px,  g_x);
    cudaGetSymbolAddress((void**)&ph1, g_h1);
    cudaGetSymbolAddress((void**)&psh, g_sh);
    cudaGetSymbolAddress((void**)&pt0, g_t0);
    cudaGetSymbolAddress((void**)&pt1, g_t1);
    cudaGetSymbolAddress((void**)&pt2, g_t2);
    cudaGetSymbolAddress((void**)&po0, g_o0);
    cudaGetSymbolAddress((void**)&po1, g_o1);
    cudaGetSymbolAddress((void**)&po2, g_o2);

    // 1) NCHW -> NHWC
    transpose_k<<<dim3(WW / 32, CHN / 32, BATCH * HH), dim3(32, 8)>>>(fm);

    // 2) rotated roi-align -> g_x [N, 2304]
    roi_k<<<NROI, CHN>>>(boxes, bidx);

    const dim3 g1(DDIM / 64, NROI / 64, 1);
    const dim3 g3(DDIM / 64, NROI / 64, 3);

    // 3) shared MLP (z=1: pass same pointers)
    gemm3_k<<<g1, 256>>>(px,  px,  px,  w_sh1, w_sh1, w_sh1, ph1, ph1, ph1, NROI, DDIM, FDIM);
    gemm3_k<<<g1, 256>>>(ph1, ph1, ph1, w_sh2, w_sh2, w_sh2, psh, psh, psh, NROI, DDIM, DDIM);

    // 4) three head branches, batched (layer 1 then layer 2)
    gemm3_k<<<g3, 256>>>(psh, psh, psh, w_cls1, w_iou1, w_reg1, pt0, pt1, pt2, NROI, DDIM, DDIM);
    gemm3_k<<<g3, 256>>>(pt0, pt1, pt2, w_cls2, w_iou2, w_reg2, po0, po1, po2, NROI, DDIM, DDIM);

    // 5) final projections -> d_out (cls[2048] | iou[2048] | reg[2048*7])
    heads_k<<<NROI, 288>>>(po0, po1, po2, w_cls3, b_cls3, w_iou3, b_iou3,
                           w_reg3, b_reg3, (float*)d_out);
}